// round 12
// baseline (speedup 1.0000x reference)
#include <cuda_runtime.h>

#define LVLS 16
#define TSIZE 16384
#define NPTS 262144
#define TMASK 16383
#define PRIME1 (-1640531535)   // 2654435761 wrapped to int32
#define PRIME2 (805459861)
#define CTAS_PER_LVL 9
#define NTHREADS 1024
#define GRIDSZ (CTAS_PER_LVL * LVLS)   // 144 CTAs, 1/SM, single co-resident wave
#define NCHUNKS 16
#define CHPTS (NPTS / NCHUNKS)         // 16384 points per chunk
#define SLICE 1821                     // ceil(CHPTS / 9) points per level-CTA per chunk
#define TILEPTS 128                    // transpose tile: 128 points x 16 levels
#define TILES_PER_CHUNK (CHPTS / TILEPTS)   // 128 tiles; CTAs 0..127 take one each
#define TPITCH 130                     // float2 pitch of tile rows (2-way LDS ok)

// Scratch in (L, N) layout of float2 — 33.5MB static device array (allowed).
__device__ float2 g_scr[(size_t)LVLS * NPTS];
// Per-chunk monotonic counters: +GRIDSZ per kernel run, never reset.
// Targets derive from each CTA's own returned old value -> replay-safe.
__device__ unsigned int g_cnt[NCHUNKS];

// ---------------------------------------------------------------------------
// Fused software-pipelined kernel. Per CTA (level, slice), per chunk c:
//   1) gather chunk c's slice into scratch (smem table, all 1024 threads)
//   2) publish chunk c (one release-atomic after __syncthreads)
//   3) transpose one tile of chunk c-1 (tiny: 1 LDG.128/STS/LDS/STG per thread)
// The transpose's LTS-bound traffic rides in the gather's L2-bandwidth slack.
// ---------------------------------------------------------------------------
__global__ __launch_bounds__(NTHREADS, 1)
void hash_enc_pipe(const float* __restrict__ x,
                   const float* __restrict__ emb,
                   float* __restrict__ out)
{
    extern __shared__ float2 smem[];                 // [0,TSIZE): table
    float2 (*tile)[TPITCH] = (float2 (*)[TPITCH])(smem + TSIZE);  // 16.6KB

    const int level = blockIdx.y;
    const int s     = blockIdx.x;                    // 0..8 slice within level
    const int bid   = blockIdx.y * CTAS_PER_LVL + blockIdx.x;   // 0..143
    const int tid   = threadIdx.x;

    // ---- table load (ONCE) ----
    {
        const float4* src = (const float4*)(emb + (size_t)level * TSIZE * 2);
        float4* dst = (float4*)smem;
        #pragma unroll
        for (int i = tid; i < (TSIZE * 2) / 4; i += NTHREADS)
            dst[i] = src[i];
    }
    __syncthreads();

    // Per-level resolution (identical formula — index math unchanged)
    const float bgrow = expf((logf(512.0f) - logf(16.0f)) * (1.0f / 16.0f));
    const float scale = 16.0f * powf(bgrow, (float)level);
    float2* scr = g_scr + (size_t)level * NPTS;

    const float4* scr4 = (const float4*)g_scr;
    float4* out4 = (float4*)out;
    const int l_ld   = tid >> 6;           // transpose-load level (0..15)
    const int slot   = tid & 63;           // transpose-load float4 slot (0..63)
    const int q      = tid & 7;            // transpose-store float4 slot in row
    const int pr     = tid >> 3;           // transpose-store point row (0..127)

    unsigned int tprev = 0;                // thread 0 only: prior chunk's target

    for (int c = 0; c < NCHUNKS; ++c) {
        // ---------- 1) gather chunk c slice ----------
        const int cbase = c * CHPTS;
        const int start = cbase + s * SLICE;
        const int end   = min(start + SLICE, cbase + CHPTS);
        for (int n = start + tid; n < end; n += NTHREADS) {
            const float x0 = x[n * 3 + 0];
            const float x1 = x[n * 3 + 1];
            const float x2 = x[n * 3 + 2];

            const float u0 = x0 * scale, u1 = x1 * scale, u2 = x2 * scale;
            const float f0 = floorf(u0), f1 = floorf(u1), f2 = floorf(u2);
            const int   i0 = (int)f0,    i1 = (int)f1,    i2 = (int)f2;
            const float d0 = u0 - f0, d1 = u1 - f1, d2 = u2 - f2;
            const float o0 = 1.0f - d0, o1 = 1.0f - d1, o2 = 1.0f - d2;

            const int pl0 = i0;            const int ph0 = pl0 + 1;
            const int pl1 = i1 * PRIME1;   const int ph1 = pl1 + PRIME1;
            const int pl2 = i2 * PRIME2;   const int ph2 = pl2 + PRIME2;
            // frac==0 corners carry exactly-zero weight: hi = lo+1 safe.

            float ax = 0.0f, ay = 0.0f;
            #pragma unroll
            for (int k = 0; k < 8; ++k) {
                const int a  = (k >> 2) & 1;
                const int b  = (k >> 1) & 1;
                const int cc = k & 1;
                const int h = (a ? ph0 : pl0) ^ (b ? ph1 : pl1) ^ (cc ? ph2 : pl2);
                const int idx = h & TMASK;
                const float w = (a ? d0 : o0) * (b ? d1 : o1) * (cc ? d2 : o2);
                const float2 v = smem[idx];
                ax = fmaf(w, v.x, ax);
                ay = fmaf(w, v.y, ay);
            }
            scr[n] = make_float2(ax, ay);   // coalesced 256B warp store
        }

        // ---------- 2) publish chunk c ----------
        __syncthreads();                    // all slice stores issued (block-wide)
        unsigned int oldc = 0;
        if (tid == 0) {
            asm volatile("atom.release.gpu.global.add.u32 %0, [%1], %2;"
                         : "=r"(oldc) : "l"(&g_cnt[c]), "r"(1u) : "memory");
        }

        // ---------- 3) transpose one tile of chunk c-1 ----------
        if (c > 0) {
            if (tid == 0) {                 // wait: all 144 published chunk c-1
                for (;;) {
                    unsigned int v;
                    asm volatile("ld.acquire.gpu.global.u32 %0, [%1];"
                                 : "=r"(v) : "l"(&g_cnt[c - 1]) : "memory");
                    if (v >= tprev) break;
                    __nanosleep(64);
                }
            }
            __syncthreads();                // readiness + visibility to block
            if (bid < TILES_PER_CHUNK) {
                const int n0 = (c - 1) * CHPTS + bid * TILEPTS;
                const float4 v = __ldcg(scr4 + (size_t)l_ld * (NPTS / 2)
                                        + (n0 >> 1) + slot);
                *(float4*)&tile[l_ld][2 * slot] = v;     // STS.128, conflict-free
                __syncthreads();
                const float2 a = tile[2 * q][pr];
                const float2 b = tile[2 * q + 1][pr];
                out4[(size_t)(n0 + pr) * (LVLS / 2) + q]
                    = make_float4(a.x, a.y, b.x, b.y);   // 512B/warp contiguous
                __syncthreads();            // tile reusable next chunk
            }
        }
        if (tid == 0) tprev = (oldc / GRIDSZ + 1u) * GRIDSZ;
    }

    // ---------- tail: transpose last chunk ----------
    if (tid == 0) {
        for (;;) {
            unsigned int v;
            asm volatile("ld.acquire.gpu.global.u32 %0, [%1];"
                         : "=r"(v) : "l"(&g_cnt[NCHUNKS - 1]) : "memory");
            if (v >= tprev) break;
            __nanosleep(64);
        }
    }
    __syncthreads();
    if (bid < TILES_PER_CHUNK) {
        const int n0 = (NCHUNKS - 1) * CHPTS + bid * TILEPTS;
        const float4 v = __ldcg(scr4 + (size_t)l_ld * (NPTS / 2) + (n0 >> 1) + slot);
        *(float4*)&tile[l_ld][2 * slot] = v;
        __syncthreads();
        const float2 a = tile[2 * q][pr];
        const float2 b = tile[2 * q + 1][pr];
        out4[(size_t)(n0 + pr) * (LVLS / 2) + q] = make_float4(a.x, a.y, b.x, b.y);
    }
}

extern "C" void kernel_launch(void* const* d_in, const int* in_sizes, int n_in,
                              void* d_out, int out_size)
{
    const float* x;
    const float* emb;
    if (in_sizes[0] == NPTS * 3) {
        x = (const float*)d_in[0];
        emb = (const float*)d_in[1];
    } else {
        x = (const float*)d_in[1];
        emb = (const float*)d_in[0];
    }
    float* out = (float*)d_out;

    const int smem_bytes = TSIZE * 2 * (int)sizeof(float)        // table 128KB
                         + LVLS * TPITCH * (int)sizeof(float2);  // tile 16.6KB
    cudaFuncSetAttribute(hash_enc_pipe,
                         cudaFuncAttributeMaxDynamicSharedMemorySize,
                         smem_bytes);

    dim3 grid(CTAS_PER_LVL, LVLS);   // 144 CTAs = one full wave @ 1 CTA/SM
    hash_enc_pipe<<<grid, NTHREADS, smem_bytes>>>(x, emb, out);
}

// round 13
// speedup vs baseline: 1.6324x; 1.6324x over previous
#include <cuda_runtime.h>

#define LVLS 16
#define TSIZE 16384
#define NPTS 262144
#define NPAIRS (NPTS / 2)
#define TMASK 16383
#define PRIME1 (-1640531535)   // 2654435761 wrapped to int32
#define PRIME2 (805459861)
#define CTAS_PER_LVL 9
#define NTHREADS 1024
#define TPTS 256               // points per transpose tile
#define TPITCH 17              // level pitch in transpose tile

// Scratch in (L, N) layout of float2 — 33.5MB static device array (allowed).
__device__ float2 g_scr[(size_t)LVLS * NPTS];

// ---------------------------------------------------------------------------
// Per-point hash-grid computation (identical arithmetic to the passing
// kernels — index math must stay bit-exact).
// ---------------------------------------------------------------------------
__device__ __forceinline__ float2 hash_point(const float2* __restrict__ table,
                                             float x0, float x1, float x2,
                                             float scale)
{
    const float u0 = x0 * scale, u1 = x1 * scale, u2 = x2 * scale;
    const float f0 = floorf(u0), f1 = floorf(u1), f2 = floorf(u2);
    const int   i0 = (int)f0,    i1 = (int)f1,    i2 = (int)f2;
    // d = ceil-floor is 1 when frac>0, else 0 -> diff == frac either way.
    const float d0 = u0 - f0, d1 = u1 - f1, d2 = u2 - f2;
    const float o0 = 1.0f - d0, o1 = 1.0f - d1, o2 = 1.0f - d2;

    // Pre-multiplied corner hash terms (wrapping int32, matches jnp/torch)
    const int pl0 = i0;                  const int ph0 = pl0 + 1;
    const int pl1 = i1 * PRIME1;         const int ph1 = pl1 + PRIME1;
    const int pl2 = i2 * PRIME2;         const int ph2 = pl2 + PRIME2;
    // frac==0 corners carry an exactly-zero weight, so hi = lo+1 is safe.

    float ax = 0.0f, ay = 0.0f;
    #pragma unroll
    for (int k = 0; k < 8; ++k) {
        const int a  = (k >> 2) & 1;
        const int b  = (k >> 1) & 1;
        const int c  = k & 1;
        const int h = (a ? ph0 : pl0) ^ (b ? ph1 : pl1) ^ (c ? ph2 : pl2);
        const int idx = h & TMASK;      // == mod 16384 for int32
        const float w = (a ? d0 : o0) * (b ? d1 : o1) * (c ? d2 : o2);
        const float2 v = table[idx];
        ax = fmaf(w, v.x, ax);
        ay = fmaf(w, v.y, ay);
    }
    return make_float2(ax, ay);
}

// ---------------------------------------------------------------------------
// Kernel 1: hash-grid gather, 2 points per thread. One CTA per (level,
// slice); the level's 128KB table lives in shared memory.
//   - x loads: 3x LDG.64 per thread (8B-aligned), 3 wavefronts per 32 points
//     (was 9 with scalar loads).
//   - two independent gather/FMA chains per thread -> 2x ILP on LDS latency.
//   - store: one st.v4 (16B) per thread, 512B contiguous per warp.
// ---------------------------------------------------------------------------
__global__ __launch_bounds__(NTHREADS, 1)
void hash_enc_kernel(const float* __restrict__ x,
                     const float* __restrict__ emb)
{
    extern __shared__ float2 table[];   // TSIZE float2 = 128KB
    const int level = blockIdx.y;

    // Cooperative table load (float4-vectorized, coalesced)
    {
        const float4* src = (const float4*)(emb + (size_t)level * TSIZE * 2);
        float4* dst = (float4*)table;
        #pragma unroll
        for (int i = threadIdx.x; i < (TSIZE * 2) / 4; i += NTHREADS)
            dst[i] = src[i];
    }
    __syncthreads();

    // Per-level resolution: N_l = Nmin * b^l (identical formula)
    const float bgrow = expf((logf(512.0f) - logf(16.0f)) * (1.0f / 16.0f));
    const float scale = 16.0f * powf(bgrow, (float)level);

    const float2* x2 = (const float2*)x;
    float4* scr4 = (float4*)(g_scr + (size_t)level * NPTS);

    const int stride = CTAS_PER_LVL * NTHREADS;
    for (int p = blockIdx.x * NTHREADS + threadIdx.x; p < NPAIRS; p += stride) {
        // 6 floats = points 2p and 2p+1, three aligned float2 loads
        const float2 va = x2[3 * p + 0];   // xA0, xA1
        const float2 vb = x2[3 * p + 1];   // xA2, xB0
        const float2 vc = x2[3 * p + 2];   // xB1, xB2

        const float2 rA = hash_point(table, va.x, va.y, vb.x, scale);
        const float2 rB = hash_point(table, vb.y, vc.x, vc.y, scale);

        // (L, N, 2) scratch layout: 16B store, 512B contiguous per warp
        scr4[p] = make_float4(rA.x, rA.y, rB.x, rB.y);
    }
}

// ---------------------------------------------------------------------------
// Kernel 2: (L, N, 2) -> (N, L*2) transpose (best-measured R5 variant).
// 256-point tiles; both gmem sides coalesced; warp writes 4 consecutive
// full 128B output rows per STG.128 pass.
// ---------------------------------------------------------------------------
__global__ __launch_bounds__(TPTS)
void transpose_kernel(float* __restrict__ out)
{
    __shared__ float2 tile[TPTS][TPITCH];   // 256 x 17 x 8B = 34.8KB

    const int n0 = blockIdx.x * TPTS;
    const int t  = threadIdx.x;

    // Load: per level, 256 consecutive float2 (coalesced);
    // smem banks = (34t + 2l) % 32 -> distinct across lanes.
    #pragma unroll
    for (int l = 0; l < LVLS; ++l)
        tile[t][l] = g_scr[(size_t)l * NPTS + n0 + t];
    __syncthreads();

    // Store: warp writes 4 consecutive 128B output rows per pass.
    const int q  = t & 7;    // float4 (pair of levels) within the row
    const int pl = t >> 3;   // point-within-tile offset
    float4* out4 = (float4*)out;
    #pragma unroll
    for (int i = 0; i < TPTS / 32; ++i) {
        const int p = i * 32 + pl;
        const float2 a = tile[p][2 * q];
        const float2 b = tile[p][2 * q + 1];
        out4[(size_t)(n0 + p) * (LVLS / 2) + q] = make_float4(a.x, a.y, b.x, b.y);
    }
}

extern "C" void kernel_launch(void* const* d_in, const int* in_sizes, int n_in,
                              void* d_out, int out_size)
{
    const float* x;
    const float* emb;
    if (in_sizes[0] == NPTS * 3) {
        x = (const float*)d_in[0];
        emb = (const float*)d_in[1];
    } else {
        x = (const float*)d_in[1];
        emb = (const float*)d_in[0];
    }
    float* out = (float*)d_out;

    cudaFuncSetAttribute(hash_enc_kernel,
                         cudaFuncAttributeMaxDynamicSharedMemorySize,
                         TSIZE * 2 * (int)sizeof(float));

    dim3 grid(CTAS_PER_LVL, LVLS);   // 144 CTAs = one full wave @ 1 CTA/SM
    hash_enc_kernel<<<grid, NTHREADS, TSIZE * 2 * sizeof(float)>>>(x, emb);

    transpose_kernel<<<NPTS / TPTS, TPTS>>>(out);
}